// round 1
// baseline (speedup 1.0000x reference)
#include <cuda_runtime.h>
#include <cstdint>
#include <cstddef>

// Problem constants
#define E_DIM   28
#define N_HEAD  4
#define HD_DIM  7
#define FF_DIM  256
#define LMAX_C  8
#define T_DIM   512
#define B_DIM   64
#define S_DIM   4096

typedef unsigned long long u64;

// ---------------- packed f32x2 helpers (sm_100+) ----------------
static __device__ __forceinline__ u64 ffma2(u64 a, u64 b, u64 c) {
    u64 d; asm("fma.rn.f32x2 %0,%1,%2,%3;" : "=l"(d) : "l"(a), "l"(b), "l"(c)); return d;
}
static __device__ __forceinline__ u64 f2pack(float lo, float hi) {
    u64 r; asm("mov.b64 %0,{%1,%2};" : "=l"(r) : "f"(lo), "f"(hi)); return r;
}
static __device__ __forceinline__ void f2unpack(u64 a, float& lo, float& hi) {
    asm("mov.b64 {%0,%1},%2;" : "=f"(lo), "=f"(hi) : "l"(a));
}
// 16B shared load -> two f32x2 (LDS.128), addr is 32-bit shared-window address
static __device__ __forceinline__ void lds_v2u64(uint32_t addr, u64& x, u64& y) {
    asm("ld.shared.v2.b64 {%0,%1},[%2];" : "=l"(x), "=l"(y) : "r"(addr));
}

// dot product of a 28-float register vector (as 14 f32x2) with a 28-float smem row
static __device__ __forceinline__ float dot28(const u64* a, uint32_t waddr) {
    u64 acc0 = 0ull, acc1 = 0ull;
#pragma unroll
    for (int i = 0; i < 7; i++) {
        u64 w0, w1; lds_v2u64(waddr + 16u * i, w0, w1);
        acc0 = ffma2(a[2 * i],     w0, acc0);
        acc1 = ffma2(a[2 * i + 1], w1, acc1);
    }
    float l0, h0, l1, h1;
    f2unpack(acc0, l0, h0); f2unpack(acc1, l1, h1);
    return (l0 + h0) + (l1 + h1);
}

// ---------------- smem layout (floats) ----------------
// w_in[84*28] @0, b_in[84] @2352, w_out[28*28] @2436, b_out[28] @3220,
// ln1g[28] @3248, ln1b[28] @3276, w1[256*28] @3304, b1[256] @10472,
// w2t[256*28] @10728, b2[28] @17896, ln2g[28] @17924, ln2b[28] @17952,
// pad[28] @17980 ; total = 18008 floats = 72032 bytes
#define OFF_WIN  0
#define OFF_BIN  2352
#define OFF_WOUT 2436
#define OFF_BOUT 3220
#define OFF_LN1G 3248
#define OFF_LN1B 3276
#define OFF_W1   3304
#define OFF_B1   10472
#define OFF_W2T  10728
#define OFF_B2   17896
#define OFF_LN2G 17924
#define OFF_LN2B 17952
#define OFF_PAD  17980
#define SMEM_FLOATS 18008
#define SMEM_BYTES  (SMEM_FLOATS * 4)

extern __shared__ float smem[];

__global__ void __launch_bounds__(256)
span_transformer_kernel(const float* __restrict__ emb,
                        const int* __restrict__ span_lengths,
                        const int* __restrict__ num_spans,
                        const float* __restrict__ w_in,  const float* __restrict__ b_in,
                        const float* __restrict__ w_out, const float* __restrict__ b_out,
                        const float* __restrict__ ln1g,  const float* __restrict__ ln1b,
                        const float* __restrict__ w1,    const float* __restrict__ b1,
                        const float* __restrict__ w2,    const float* __restrict__ b2,
                        const float* __restrict__ ln2g,  const float* __restrict__ ln2b,
                        const float* __restrict__ pad_tok,
                        float* __restrict__ out)
{
    const int tid = threadIdx.x;

    // ---- stage weights into shared memory (uniform-broadcast reads later) ----
    for (int i = tid; i < 84 * E_DIM; i += 256) smem[OFF_WIN + i] = w_in[i];
    for (int i = tid; i < 84;         i += 256) smem[OFF_BIN + i] = b_in[i];
    for (int i = tid; i < E_DIM * E_DIM; i += 256) smem[OFF_WOUT + i] = w_out[i];
    if (tid < E_DIM) {
        smem[OFF_BOUT + tid] = b_out[tid];
        smem[OFF_LN1G + tid] = ln1g[tid];
        smem[OFF_LN1B + tid] = ln1b[tid];
        smem[OFF_B2   + tid] = b2[tid];
        smem[OFF_LN2G + tid] = ln2g[tid];
        smem[OFF_LN2B + tid] = ln2b[tid];
        smem[OFF_PAD  + tid] = pad_tok[tid];
    }
    for (int i = tid; i < FF_DIM * E_DIM; i += 256) smem[OFF_W1 + i] = w1[i];
    for (int i = tid; i < FF_DIM;         i += 256) smem[OFF_B1 + i] = b1[i];
    // transpose lin2_w [E][FF] -> w2t [FF][E]
    for (int i = tid; i < FF_DIM * E_DIM; i += 256) {
        int f = i / E_DIM;
        int e = i - f * E_DIM;
        smem[OFF_W2T + i] = w2[e * FF_DIM + f];
    }
    __syncthreads();

    // ---- task mapping: warp = 4 consecutive spans of one batch; lane = (span, token) ----
    const int warpId = blockIdx.x * 8 + (tid >> 5);   // 0..8191
    const int lane   = tid & 31;
    const int l      = lane & 7;     // token within span
    const int sp     = lane >> 3;    // span within warp (0..3)
    const int b      = warpId >> 7;          // batch
    const int tbase  = (warpId & 127) << 2;  // first span index of this warp
    const int t      = tbase + sp;

    const int ns  = num_spans[b];
    const int len = span_lengths[b * T_DIM + t];

    const uint32_t sb = (uint32_t)__cvta_generic_to_shared(smem);
    float* outrow = out + (size_t)(b * T_DIM + t) * E_DIM;

    // whole-warp invalid fast path
    if (tbase >= ns) {
        if (l == 0) {
#pragma unroll
            for (int i = 0; i < 7; i++)
                reinterpret_cast<float4*>(outrow)[i] =
                    reinterpret_cast<const float4*>(smem + OFF_PAD)[i];
        }
        return;
    }

    // ---- load this token's 28-dim embedding ----
    u64 x2[14];
    {
        const float4* xr = reinterpret_cast<const float4*>(
            emb + ((size_t)b * S_DIM + (size_t)t * 8 + l) * E_DIM);
#pragma unroll
        for (int i = 0; i < 7; i++) {
            union { float4 f4; u64 u[2]; } u;
            u.f4 = xr[i];
            x2[2 * i] = u.u[0]; x2[2 * i + 1] = u.u[1];
        }
    }

    // ---- qkv projection ----
    float q[E_DIM], k[E_DIM], v[E_DIM];
#pragma unroll
    for (int f = 0; f < E_DIM; f++) {
        q[f] = dot28(x2, sb + (uint32_t)((OFF_WIN) * 4 + f * 112))        + smem[OFF_BIN + f];
        k[f] = dot28(x2, sb + (uint32_t)((OFF_WIN) * 4 + (28 + f) * 112)) + smem[OFF_BIN + 28 + f];
        v[f] = dot28(x2, sb + (uint32_t)((OFF_WIN) * 4 + (56 + f) * 112)) + smem[OFF_BIN + 56 + f];
    }

    // ---- attention within the 8-token span (shfl across the 8-lane group) ----
    const int gbase = lane & 24;
    const float scale = 0.3779644730092272f; // 1/sqrt(7)
#pragma unroll
    for (int h = 0; h < N_HEAD; h++) {
        float s[LMAX_C];
#pragma unroll
        for (int l2 = 0; l2 < LMAX_C; l2++) {
            float acc = 0.f;
#pragma unroll
            for (int d = 0; d < HD_DIM; d++) {
                float kk = __shfl_sync(0xffffffffu, k[h * HD_DIM + d], gbase + l2);
                acc = fmaf(q[h * HD_DIM + d], kk, acc);
            }
            s[l2] = acc * scale;
        }
        float m = s[0];
#pragma unroll
        for (int l2 = 1; l2 < LMAX_C; l2++) if (l2 < len) m = fmaxf(m, s[l2]);
        float ssum = 0.f;
#pragma unroll
        for (int l2 = 0; l2 < LMAX_C; l2++) {
            float ev = (l2 < len) ? __expf(s[l2] - m) : 0.f;
            s[l2] = ev; ssum += ev;
        }
        float inv = 1.f / ssum;
#pragma unroll
        for (int l2 = 0; l2 < LMAX_C; l2++) s[l2] *= inv;
#pragma unroll
        for (int d = 0; d < HD_DIM; d++) {
            float acc = 0.f;
#pragma unroll
            for (int l2 = 0; l2 < LMAX_C; l2++) {
                float vv = __shfl_sync(0xffffffffu, v[h * HD_DIM + d], gbase + l2);
                acc = fmaf(s[l2], vv, acc);
            }
            q[h * HD_DIM + d] = acc; // overwrite q with attention output
        }
    }

    // ---- output projection + residual + LN1 ----
    u64 ao2[14];
#pragma unroll
    for (int j = 0; j < 14; j++) ao2[j] = f2pack(q[2 * j], q[2 * j + 1]);

    float r[E_DIM];
#pragma unroll
    for (int j = 0; j < 14; j++) {
        float xlo, xhi; f2unpack(x2[j], xlo, xhi);
        r[2 * j]     = dot28(ao2, sb + (uint32_t)(OFF_WOUT * 4 + (2 * j) * 112))
                       + smem[OFF_BOUT + 2 * j] + xlo;
        r[2 * j + 1] = dot28(ao2, sb + (uint32_t)(OFF_WOUT * 4 + (2 * j + 1) * 112))
                       + smem[OFF_BOUT + 2 * j + 1] + xhi;
    }
    {
        float mu = 0.f;
#pragma unroll
        for (int e = 0; e < E_DIM; e++) mu += r[e];
        mu *= (1.f / E_DIM);
        float var = 0.f;
#pragma unroll
        for (int e = 0; e < E_DIM; e++) { float d = r[e] - mu; var = fmaf(d, d, var); }
        var *= (1.f / E_DIM);
        float inv = rsqrtf(var + 1e-5f);
#pragma unroll
        for (int e = 0; e < E_DIM; e++)
            r[e] = fmaf((r[e] - mu) * inv, smem[OFF_LN1G + e], smem[OFF_LN1B + e]);
    }
#pragma unroll
    for (int j = 0; j < 14; j++) x2[j] = f2pack(r[2 * j], r[2 * j + 1]); // x1

    // ---- fused FF: h = relu(x1 @ w1^T + b1); ff += h * w2t[f] ----
    u64 ffa[14];
#pragma unroll
    for (int j = 0; j < 14; j++)
        ffa[j] = f2pack(smem[OFF_B2 + 2 * j], smem[OFF_B2 + 2 * j + 1]);

#pragma unroll 4
    for (int f = 0; f < FF_DIM; f++) {
        float hv = dot28(x2, sb + (uint32_t)(OFF_W1 * 4 + f * 112)) + smem[OFF_B1 + f];
        hv = fmaxf(hv, 0.f);
        u64 h2 = f2pack(hv, hv);
        uint32_t wa = sb + (uint32_t)(OFF_W2T * 4 + f * 112);
#pragma unroll
        for (int i = 0; i < 7; i++) {
            u64 w0, w1v; lds_v2u64(wa + 16u * i, w0, w1v);
            ffa[2 * i]     = ffma2(h2, w0,  ffa[2 * i]);
            ffa[2 * i + 1] = ffma2(h2, w1v, ffa[2 * i + 1]);
        }
    }

    // ---- residual + LN2 ----
#pragma unroll
    for (int j = 0; j < 14; j++) {
        float flo, fhi, xlo, xhi;
        f2unpack(ffa[j], flo, fhi); f2unpack(x2[j], xlo, xhi);
        r[2 * j] = flo + xlo; r[2 * j + 1] = fhi + xhi;
    }
    {
        float mu = 0.f;
#pragma unroll
        for (int e = 0; e < E_DIM; e++) mu += r[e];
        mu *= (1.f / E_DIM);
        float var = 0.f;
#pragma unroll
        for (int e = 0; e < E_DIM; e++) { float d = r[e] - mu; var = fmaf(d, d, var); }
        var *= (1.f / E_DIM);
        float inv = rsqrtf(var + 1e-5f);
#pragma unroll
        for (int e = 0; e < E_DIM; e++)
            r[e] = fmaf((r[e] - mu) * inv, smem[OFF_LN2G + e], smem[OFF_LN2B + e]);
    }

    // ---- masked mean pool across the 8 tokens (butterfly within 8-lane group) ----
    const float wm = (l < len) ? 1.f : 0.f;
#pragma unroll
    for (int e = 0; e < E_DIM; e++) {
        float vv = r[e] * wm;
        vv += __shfl_xor_sync(0xffffffffu, vv, 1);
        vv += __shfl_xor_sync(0xffffffffu, vv, 2);
        vv += __shfl_xor_sync(0xffffffffu, vv, 4);
        r[e] = vv;
    }

    if (l == 0) {
        if (t < ns) {
            const float invlen = 1.f / (float)len;
#pragma unroll
            for (int i = 0; i < 7; i++) {
                float4 o;
                o.x = r[4 * i]     * invlen;
                o.y = r[4 * i + 1] * invlen;
                o.z = r[4 * i + 2] * invlen;
                o.w = r[4 * i + 3] * invlen;
                reinterpret_cast<float4*>(outrow)[i] = o;
            }
        } else {
#pragma unroll
            for (int i = 0; i < 7; i++)
                reinterpret_cast<float4*>(outrow)[i] =
                    reinterpret_cast<const float4*>(smem + OFF_PAD)[i];
        }
    }
}

extern "C" void kernel_launch(void* const* d_in, const int* in_sizes, int n_in,
                              void* d_out, int out_size)
{
    const float* emb          = (const float*)d_in[0];
    const int*   span_lengths = (const int*)  d_in[1];
    const int*   num_spans    = (const int*)  d_in[2];
    const float* w_in         = (const float*)d_in[3];
    const float* b_in         = (const float*)d_in[4];
    const float* w_out        = (const float*)d_in[5];
    const float* b_out        = (const float*)d_in[6];
    const float* ln1g         = (const float*)d_in[7];
    const float* ln1b         = (const float*)d_in[8];
    const float* w1           = (const float*)d_in[9];
    const float* b1           = (const float*)d_in[10];
    const float* w2           = (const float*)d_in[11];
    const float* b2           = (const float*)d_in[12];
    const float* ln2g         = (const float*)d_in[13];
    const float* ln2b         = (const float*)d_in[14];
    const float* pad_tok      = (const float*)d_in[15];
    float* out = (float*)d_out;

    (void)in_sizes; (void)n_in; (void)out_size;

    cudaFuncSetAttribute(span_transformer_kernel,
                         cudaFuncAttributeMaxDynamicSharedMemorySize, SMEM_BYTES);

    // 8192 warp-tasks (B * T/4), 8 warps per CTA
    span_transformer_kernel<<<1024, 256, SMEM_BYTES>>>(
        emb, span_lengths, num_spans,
        w_in, b_in, w_out, b_out, ln1g, ln1b,
        w1, b1, w2, b2, ln2g, ln2b, pad_tok, out);
}

// round 2
// speedup vs baseline: 1.0661x; 1.0661x over previous
#include <cuda_runtime.h>
#include <cstdint>
#include <cstddef>

// Problem constants
#define E_DIM   28
#define N_HEAD  4
#define HD_DIM  7
#define FF_DIM  256
#define LMAX_C  8
#define T_DIM   512
#define B_DIM   64
#define S_DIM   4096

typedef unsigned long long u64;

// ---------------- packed f32x2 helpers (sm_100+) ----------------
static __device__ __forceinline__ u64 ffma2(u64 a, u64 b, u64 c) {
    u64 d; asm("fma.rn.f32x2 %0,%1,%2,%3;" : "=l"(d) : "l"(a), "l"(b), "l"(c)); return d;
}
static __device__ __forceinline__ u64 addf2(u64 a, u64 b) {
    u64 d; asm("add.rn.f32x2 %0,%1,%2;" : "=l"(d) : "l"(a), "l"(b)); return d;
}
static __device__ __forceinline__ u64 f2pack(float lo, float hi) {
    u64 r; asm("mov.b64 %0,{%1,%2};" : "=l"(r) : "f"(lo), "f"(hi)); return r;
}
static __device__ __forceinline__ void f2unpack(u64 a, float& lo, float& hi) {
    asm("mov.b64 {%0,%1},%2;" : "=f"(lo), "=f"(hi) : "l"(a));
}
// 16B shared load -> two f32x2 (LDS.128), addr is 32-bit shared-window address
static __device__ __forceinline__ void lds_v2u64(uint32_t addr, u64& x, u64& y) {
    asm("ld.shared.v2.b64 {%0,%1},[%2];" : "=l"(x), "=l"(y) : "r"(addr));
}

// dot of 28-float register vector (14 f32x2) with 28-float smem row.
// 4 independent accumulator chains (depth 4) + packed-f32x2 reduction.
static __device__ __forceinline__ float dot28(const u64* a, uint32_t waddr) {
    u64 acc0 = 0ull, acc1 = 0ull, acc2 = 0ull, acc3 = 0ull;
    {
        u64 w0, w1, w2, w3;
        lds_v2u64(waddr,        w0, w1);
        lds_v2u64(waddr + 16u,  w2, w3);
        acc0 = ffma2(a[0], w0, acc0);
        acc1 = ffma2(a[1], w1, acc1);
        acc2 = ffma2(a[2], w2, acc2);
        acc3 = ffma2(a[3], w3, acc3);
        lds_v2u64(waddr + 32u,  w0, w1);
        lds_v2u64(waddr + 48u,  w2, w3);
        acc0 = ffma2(a[4], w0, acc0);
        acc1 = ffma2(a[5], w1, acc1);
        acc2 = ffma2(a[6], w2, acc2);
        acc3 = ffma2(a[7], w3, acc3);
        lds_v2u64(waddr + 64u,  w0, w1);
        lds_v2u64(waddr + 80u,  w2, w3);
        acc0 = ffma2(a[8],  w0, acc0);
        acc1 = ffma2(a[9],  w1, acc1);
        acc2 = ffma2(a[10], w2, acc2);
        acc3 = ffma2(a[11], w3, acc3);
        lds_v2u64(waddr + 96u,  w0, w1);
        acc0 = ffma2(a[12], w0, acc0);
        acc1 = ffma2(a[13], w1, acc1);
    }
    u64 t = addf2(addf2(acc0, acc2), addf2(acc1, acc3));
    float lo, hi; f2unpack(t, lo, hi);
    return lo + hi;
}

// ---------------- smem layout (floats) ----------------
#define OFF_WIN  0
#define OFF_BIN  2352
#define OFF_WOUT 2436
#define OFF_BOUT 3220
#define OFF_LN1G 3248
#define OFF_LN1B 3276
#define OFF_W1   3304
#define OFF_B1   10472
#define OFF_W2T  10728
#define OFF_B2   17896
#define OFF_LN2G 17924
#define OFF_LN2B 17952
#define OFF_PAD  17980
#define SMEM_FLOATS 18008
#define SMEM_BYTES  (SMEM_FLOATS * 4)

extern __shared__ float smem[];

__global__ void __launch_bounds__(256, 2)
span_transformer_kernel(const float* __restrict__ emb,
                        const int* __restrict__ span_lengths,
                        const int* __restrict__ num_spans,
                        const float* __restrict__ w_in,  const float* __restrict__ b_in,
                        const float* __restrict__ w_out, const float* __restrict__ b_out,
                        const float* __restrict__ ln1g,  const float* __restrict__ ln1b,
                        const float* __restrict__ w1,    const float* __restrict__ b1,
                        const float* __restrict__ w2,    const float* __restrict__ b2,
                        const float* __restrict__ ln2g,  const float* __restrict__ ln2b,
                        const float* __restrict__ pad_tok,
                        float* __restrict__ out)
{
    const int tid = threadIdx.x;

    // ---- stage weights into shared memory ----
    for (int i = tid; i < 84 * E_DIM; i += 256) smem[OFF_WIN + i] = w_in[i];
    for (int i = tid; i < 84;         i += 256) smem[OFF_BIN + i] = b_in[i];
    for (int i = tid; i < E_DIM * E_DIM; i += 256) smem[OFF_WOUT + i] = w_out[i];
    if (tid < E_DIM) {
        smem[OFF_BOUT + tid] = b_out[tid];
        smem[OFF_LN1G + tid] = ln1g[tid];
        smem[OFF_LN1B + tid] = ln1b[tid];
        smem[OFF_B2   + tid] = b2[tid];
        smem[OFF_LN2G + tid] = ln2g[tid];
        smem[OFF_LN2B + tid] = ln2b[tid];
        smem[OFF_PAD  + tid] = pad_tok[tid];
    }
    for (int i = tid; i < FF_DIM * E_DIM; i += 256) smem[OFF_W1 + i] = w1[i];
    for (int i = tid; i < FF_DIM;         i += 256) smem[OFF_B1 + i] = b1[i];
    // transpose lin2_w [E][FF] -> w2t [FF][E]
    for (int i = tid; i < FF_DIM * E_DIM; i += 256) {
        int f = i / E_DIM;
        int e = i - f * E_DIM;
        smem[OFF_W2T + i] = w2[e * FF_DIM + f];
    }
    __syncthreads();

    // ---- task mapping: warp = 4 consecutive spans of one batch; lane = (span, token) ----
    const int warpId = blockIdx.x * 8 + (tid >> 5);   // 0..8191
    const int lane   = tid & 31;
    const int l      = lane & 7;     // token within span
    const int b      = warpId >> 7;          // batch
    const int tbase  = (warpId & 127) << 2;  // first span of this warp
    const int t      = tbase + (lane >> 3);

    const int ns  = num_spans[b];
    const int len = span_lengths[b * T_DIM + t];

    const uint32_t sb = (uint32_t)__cvta_generic_to_shared(smem);
    float* outrow = out + (size_t)(b * T_DIM + t) * E_DIM;

    // whole-warp invalid fast path
    if (tbase >= ns) {
        if (l == 0) {
#pragma unroll
            for (int i = 0; i < 7; i++)
                reinterpret_cast<float4*>(outrow)[i] =
                    reinterpret_cast<const float4*>(smem + OFF_PAD)[i];
        }
        return;
    }

    // ---- load this token's 28-dim embedding ----
    u64 x2[14];
    {
        const float4* xr = reinterpret_cast<const float4*>(
            emb + ((size_t)b * S_DIM + (size_t)t * 8 + l) * E_DIM);
#pragma unroll
        for (int i = 0; i < 7; i++) {
            union { float4 f4; u64 u[2]; } u;
            u.f4 = xr[i];
            x2[2 * i] = u.u[0]; x2[2 * i + 1] = u.u[1];
        }
    }

    // ---- per-head qkv projection + attention (keeps live regs low) ----
    const int gbase = lane & 24;
    const float scale = 0.3779644730092272f; // 1/sqrt(7)
    float ao[E_DIM];
#pragma unroll
    for (int h = 0; h < N_HEAD; h++) {
        float qh[HD_DIM], kh[HD_DIM], vh[HD_DIM];
#pragma unroll
        for (int d = 0; d < HD_DIM; d++) {
            const int f = h * HD_DIM + d;
            qh[d] = dot28(x2, sb + (uint32_t)(OFF_WIN * 4 + f * 112))
                    + smem[OFF_BIN + f];
            kh[d] = dot28(x2, sb + (uint32_t)(OFF_WIN * 4 + (28 + f) * 112))
                    + smem[OFF_BIN + 28 + f];
            vh[d] = dot28(x2, sb + (uint32_t)(OFF_WIN * 4 + (56 + f) * 112))
                    + smem[OFF_BIN + 56 + f];
        }
        float s[LMAX_C];
#pragma unroll
        for (int l2 = 0; l2 < LMAX_C; l2++) {
            float acc = 0.f;
#pragma unroll
            for (int d = 0; d < HD_DIM; d++) {
                float kk = __shfl_sync(0xffffffffu, kh[d], gbase + l2);
                acc = fmaf(qh[d], kk, acc);
            }
            s[l2] = acc * scale;
        }
        float m = s[0];
#pragma unroll
        for (int l2 = 1; l2 < LMAX_C; l2++) if (l2 < len) m = fmaxf(m, s[l2]);
        float ssum = 0.f;
#pragma unroll
        for (int l2 = 0; l2 < LMAX_C; l2++) {
            float ev = (l2 < len) ? __expf(s[l2] - m) : 0.f;
            s[l2] = ev; ssum += ev;
        }
        const float inv = 1.f / ssum;
#pragma unroll
        for (int d = 0; d < HD_DIM; d++) {
            float acc = 0.f;
#pragma unroll
            for (int l2 = 0; l2 < LMAX_C; l2++) {
                float vv = __shfl_sync(0xffffffffu, vh[d], gbase + l2);
                acc = fmaf(s[l2], vv, acc);
            }
            ao[h * HD_DIM + d] = acc * inv;
        }
    }

    // ---- output projection + residual + LN1 ----
    u64 ao2[14];
#pragma unroll
    for (int j = 0; j < 14; j++) ao2[j] = f2pack(ao[2 * j], ao[2 * j + 1]);

    float r[E_DIM];
#pragma unroll
    for (int e = 0; e < E_DIM; e++)
        r[e] = dot28(ao2, sb + (uint32_t)(OFF_WOUT * 4 + e * 112)) + smem[OFF_BOUT + e];
    {
        float mu = 0.f;
#pragma unroll
        for (int j = 0; j < 14; j++) {
            float xlo, xhi; f2unpack(x2[j], xlo, xhi);
            r[2 * j] += xlo; r[2 * j + 1] += xhi;
            mu += r[2 * j] + r[2 * j + 1];
        }
        mu *= (1.f / E_DIM);
        float var = 0.f;
#pragma unroll
        for (int e = 0; e < E_DIM; e++) { float d = r[e] - mu; var = fmaf(d, d, var); }
        var *= (1.f / E_DIM);
        float inv = rsqrtf(var + 1e-5f);
#pragma unroll
        for (int e = 0; e < E_DIM; e++)
            r[e] = fmaf((r[e] - mu) * inv, smem[OFF_LN1G + e], smem[OFF_LN1B + e]);
    }
    // x no longer needed: reuse x2 for x1
#pragma unroll
    for (int j = 0; j < 14; j++) x2[j] = f2pack(r[2 * j], r[2 * j + 1]);

    // ---- fused FF: h = relu(x1 @ w1^T + b1); ffa += h * w2t[f] ----
    u64 ffa[14];
#pragma unroll
    for (int j = 0; j < 14; j++)
        ffa[j] = f2pack(smem[OFF_B2 + 2 * j], smem[OFF_B2 + 2 * j + 1]);

    const uint32_t w1base  = sb + (uint32_t)(OFF_W1  * 4);
    const uint32_t w2tbase = sb + (uint32_t)(OFF_W2T * 4);
#pragma unroll 2
    for (int f = 0; f < FF_DIM; f++) {
        float hv = dot28(x2, w1base + (uint32_t)(f * 112)) + smem[OFF_B1 + f];
        hv = fmaxf(hv, 0.f);
        u64 h2 = f2pack(hv, hv);
        uint32_t wa = w2tbase + (uint32_t)(f * 112);
#pragma unroll
        for (int i = 0; i < 7; i++) {
            u64 w0, w1v; lds_v2u64(wa + 16u * i, w0, w1v);
            ffa[2 * i]     = ffma2(h2, w0,  ffa[2 * i]);
            ffa[2 * i + 1] = ffma2(h2, w1v, ffa[2 * i + 1]);
        }
    }

    // ---- residual + LN2 ----
#pragma unroll
    for (int j = 0; j < 14; j++) {
        float flo, fhi, xlo, xhi;
        f2unpack(ffa[j], flo, fhi); f2unpack(x2[j], xlo, xhi);
        r[2 * j] = flo + xlo; r[2 * j + 1] = fhi + xhi;
    }
    {
        float mu = 0.f;
#pragma unroll
        for (int e = 0; e < E_DIM; e++) mu += r[e];
        mu *= (1.f / E_DIM);
        float var = 0.f;
#pragma unroll
        for (int e = 0; e < E_DIM; e++) { float d = r[e] - mu; var = fmaf(d, d, var); }
        var *= (1.f / E_DIM);
        float inv = rsqrtf(var + 1e-5f);
#pragma unroll
        for (int e = 0; e < E_DIM; e++)
            r[e] = fmaf((r[e] - mu) * inv, smem[OFF_LN2G + e], smem[OFF_LN2B + e]);
    }

    // ---- masked mean pool across the 8 tokens (butterfly within 8-lane group) ----
    const float wm = (l < len) ? 1.f : 0.f;
#pragma unroll
    for (int e = 0; e < E_DIM; e++) {
        float vv = r[e] * wm;
        vv += __shfl_xor_sync(0xffffffffu, vv, 1);
        vv += __shfl_xor_sync(0xffffffffu, vv, 2);
        vv += __shfl_xor_sync(0xffffffffu, vv, 4);
        r[e] = vv;
    }

    if (l == 0) {
        if (t < ns) {
            const float invlen = 1.f / (float)len;
#pragma unroll
            for (int i = 0; i < 7; i++) {
                float4 o;
                o.x = r[4 * i]     * invlen;
                o.y = r[4 * i + 1] * invlen;
                o.z = r[4 * i + 2] * invlen;
                o.w = r[4 * i + 3] * invlen;
                reinterpret_cast<float4*>(outrow)[i] = o;
            }
        } else {
#pragma unroll
            for (int i = 0; i < 7; i++)
                reinterpret_cast<float4*>(outrow)[i] =
                    reinterpret_cast<const float4*>(smem + OFF_PAD)[i];
        }
    }
}

extern "C" void kernel_launch(void* const* d_in, const int* in_sizes, int n_in,
                              void* d_out, int out_size)
{
    const float* emb          = (const float*)d_in[0];
    const int*   span_lengths = (const int*)  d_in[1];
    const int*   num_spans    = (const int*)  d_in[2];
    const float* w_in         = (const float*)d_in[3];
    const float* b_in         = (const float*)d_in[4];
    const float* w_out        = (const float*)d_in[5];
    const float* b_out        = (const float*)d_in[6];
    const float* ln1g         = (const float*)d_in[7];
    const float* ln1b         = (const float*)d_in[8];
    const float* w1           = (const float*)d_in[9];
    const float* b1           = (const float*)d_in[10];
    const float* w2           = (const float*)d_in[11];
    const float* b2           = (const float*)d_in[12];
    const float* ln2g         = (const float*)d_in[13];
    const float* ln2b         = (const float*)d_in[14];
    const float* pad_tok      = (const float*)d_in[15];
    float* out = (float*)d_out;

    (void)in_sizes; (void)n_in; (void)out_size;

    cudaFuncSetAttribute(span_transformer_kernel,
                         cudaFuncAttributeMaxDynamicSharedMemorySize, SMEM_BYTES);

    span_transformer_kernel<<<1024, 256, SMEM_BYTES>>>(
        emb, span_lengths, num_spans,
        w_in, b_in, w_out, b_out, ln1g, ln1b,
        w1, b1, w2, b2, ln2g, ln2b, pad_tok, out);
}